// round 14
// baseline (speedup 1.0000x reference)
#include <cuda_runtime.h>
#include <cuda_bf16.h>
#include <math.h>
#include <stdint.h>

// Problem constants (fixed shapes)
#define NROWS 16384     // B*T (GEMM M)
#define CDIM  512       // phones (GEMM K)
#define ADIM  4096      // arcs
#define PDIM  256       // phonemes (GEMM N)

// ---------------- device scratch ----------------
// B in mma-fragment order: index ((n*32 + kt)*4 + t) holds 4 bf16 (8 bytes):
// k = 16*kt + {2t, 2t+1, 2t+8, 2t+9}. One LDG.64 per lane = full B fragment pair.
__device__ uint2 g_Mf[PDIM * 32 * 4];   // 256 KB

// ---------------- build dense M, fragment-permuted (256 blocks x 256 threads) ----------------
#define FXSCALE 16777216.0f
__global__ void __launch_bounds__(256) k_buildM(const float* __restrict__ alloW,
                                                const int* __restrict__ phone,
                                                const int* __restrict__ phoneme) {
    __shared__ int rowi[CDIM];
    const int p = blockIdx.x, t = threadIdx.x;
    rowi[t] = 0;
    rowi[t + 256] = 0;
    __syncthreads();

#pragma unroll 4
    for (int a = t; a < ADIM; a += 256) {
        if (phoneme[a] == p) {
            int fx = __float2int_rn(expf(alloW[a]) * FXSCALE);
            atomicAdd(&rowi[phone[a]], fx);
        }
    }
    __syncthreads();

    __nv_bfloat16* Mf = (__nv_bfloat16*)g_Mf;
#pragma unroll
    for (int half = 0; half < 2; half++) {
        const int c = t + half * 256;
        const int kt = c >> 4, o = c & 15;
        const int tt   = (o < 8) ? (o >> 1) : ((o - 8) >> 1);
        const int slot = (o < 8) ? (o & 1) : (2 + (o & 1));
        Mf[(((size_t)p * 32 + kt) * 4 + tt) * 4 + slot] =
            __float2bfloat16_rn((float)rowi[c] * (1.0f / FXSCALE));
    }
}

// ---------------- fused softmax + GEMM + epilogue (256 blocks x 256, occ 2) ----------------
// Tile 64x256. smem: sA [64][520] bf16 = 66560 B only. B comes straight from L2 (g_Mf).
#define MROWS 64
#define LDA2  520
#define SA_BYTES (MROWS * LDA2 * 2)
#define SMEM_GEMM SA_BYTES

__device__ __forceinline__ void mma16816(float* d, const uint32_t* a, const uint32_t* b) {
    asm volatile("mma.sync.aligned.m16n8k16.row.col.f32.bf16.bf16.f32 "
                 "{%0,%1,%2,%3}, {%4,%5,%6,%7}, {%8,%9}, {%0,%1,%2,%3};"
                 : "+f"(d[0]), "+f"(d[1]), "+f"(d[2]), "+f"(d[3])
                 : "r"(a[0]), "r"(a[1]), "r"(a[2]), "r"(a[3]), "r"(b[0]), "r"(b[1]));
}
__device__ __forceinline__ void ldsm_x4(uint32_t* r, uint32_t addr) {
    asm volatile("ldmatrix.sync.aligned.m8n8.x4.shared.b16 {%0,%1,%2,%3}, [%4];"
                 : "=r"(r[0]), "=r"(r[1]), "=r"(r[2]), "=r"(r[3]) : "r"(addr));
}
__device__ __forceinline__ uint32_t smem_u32(const void* p) {
    uint32_t a;
    asm("{ .reg .u64 t; cvta.to.shared.u64 t, %1; cvt.u32.u64 %0, t; }" : "=r"(a) : "l"(p));
    return a;
}

__global__ void __launch_bounds__(256, 2) k_gemm(const float* __restrict__ hs,
                                                 float* __restrict__ out) {
    extern __shared__ char smem[];
    __nv_bfloat16* sA   = (__nv_bfloat16*)smem;                 // [64][LDA2]
    float*         s_rs = (float*)smem;                         // reuse sA after mainloop

    const int tid  = threadIdx.x;
    const int warp = tid >> 5, lane = tid & 31;
    const int wm = warp >> 2, wn = warp & 3;   // 2 x 4 warp grid (32-row x 64-col warp tiles)
    const int g = lane >> 2, t = lane & 3;
    const int row0 = blockIdx.x * MROWS;
    const uint32_t sA_u32 = smem_u32(smem);

    // ldmatrix A lane-address components
    const int a_row  = wm * 32 + (lane & 15);
    const int a_csel = (lane >> 4) << 3;
    // B fragment base index in g_Mf: ((n*32 + kt)*4 + t), n = wn*64 + ni*8 + g
    const uint2* Bf = g_Mf + ((size_t)(wn * 64 + g) * 32) * 4 + t;

    // ---- softmax: each warp owns 8 rows, 2 rows per batch ----
    for (int b = 0; b < 4; b++) {
        float4 v[2][4];
#pragma unroll
        for (int rr = 0; rr < 2; rr++) {
            const int row = warp * 8 + b * 2 + rr;
            const float4* hp = (const float4*)(hs + (size_t)(row0 + row) * CDIM);
#pragma unroll
            for (int s = 0; s < 4; s++) v[rr][s] = hp[s * 32 + lane];
        }
#pragma unroll
        for (int rr = 0; rr < 2; rr++) {
            const int row = warp * 8 + b * 2 + rr;
            float e[16];
            float sum = 0.0f;
#pragma unroll
            for (int s = 0; s < 4; s++) {
                e[s * 4 + 0] = __expf(v[rr][s].x);
                e[s * 4 + 1] = __expf(v[rr][s].y);
                e[s * 4 + 2] = __expf(v[rr][s].z);
                e[s * 4 + 3] = __expf(v[rr][s].w);
                sum += e[s * 4 + 0] + e[s * 4 + 1] + e[s * 4 + 2] + e[s * 4 + 3];
            }
#pragma unroll
            for (int o = 16; o; o >>= 1) sum += __shfl_xor_sync(0xffffffffu, sum, o);
            const float inv = 1.0f / sum;
#pragma unroll
            for (int s = 0; s < 4; s++) {
                __nv_bfloat162 p0 = __floats2bfloat162_rn(e[s * 4 + 0] * inv, e[s * 4 + 1] * inv);
                __nv_bfloat162 p1 = __floats2bfloat162_rn(e[s * 4 + 2] * inv, e[s * 4 + 3] * inv);
                uint2 w;
                w.x = *(uint32_t*)&p0;
                w.y = *(uint32_t*)&p1;
                *(uint2*)(sA + row * LDA2 + s * 128 + lane * 4) = w;
            }
        }
    }
    __syncthreads();  // sA fully built — the ONLY barrier before the epilogue

    // ---- mainloop: 32 kt steps, barrier-free; B straight from L2 ----
    float acc[2][8][4];
#pragma unroll
    for (int mi = 0; mi < 2; mi++)
#pragma unroll
        for (int ni = 0; ni < 8; ni++)
#pragma unroll
            for (int f = 0; f < 4; f++) acc[mi][ni][f] = 0.0f;

#pragma unroll 2
    for (int kt = 0; kt < 32; kt++) {
        uint32_t afr[2][4];
#pragma unroll
        for (int mi = 0; mi < 2; mi++)
            ldsm_x4(afr[mi], sA_u32 + ((a_row + mi * 16) * LDA2 + kt * 16 + a_csel) * 2);

        uint2 bv[8];
#pragma unroll
        for (int ni = 0; ni < 8; ni++)
            bv[ni] = Bf[(size_t)ni * 8 * 32 * 4 + kt * 4];

#pragma unroll
        for (int ni = 0; ni < 8; ni++) {
            mma16816(acc[0][ni], afr[0], (const uint32_t*)&bv[ni]);
            mma16816(acc[1][ni], afr[1], (const uint32_t*)&bv[ni]);
        }
    }
    __syncthreads();  // mainloop done; sA reusable as s_rs

    // ---- epilogue: deterministic per-row sums via per-warp smem slices ----
    float psum[2][2];
#pragma unroll
    for (int mi = 0; mi < 2; mi++) {
        float s0 = 0.0f, s1 = 0.0f;
#pragma unroll
        for (int ni = 0; ni < 8; ni++) {
            s0 += acc[mi][ni][0] + acc[mi][ni][1];
            s1 += acc[mi][ni][2] + acc[mi][ni][3];
        }
        s0 += __shfl_xor_sync(0xffffffffu, s0, 1);
        s0 += __shfl_xor_sync(0xffffffffu, s0, 2);
        s1 += __shfl_xor_sync(0xffffffffu, s1, 1);
        s1 += __shfl_xor_sync(0xffffffffu, s1, 2);
        psum[mi][0] = s0;
        psum[mi][1] = s1;
    }
    if (t == 0) {
#pragma unroll
        for (int mi = 0; mi < 2; mi++) {
            s_rs[wn * MROWS + wm * 32 + mi * 16 + g]     = psum[mi][0];
            s_rs[wn * MROWS + wm * 32 + mi * 16 + g + 8] = psum[mi][1];
        }
    }
    __syncthreads();

#pragma unroll
    for (int mi = 0; mi < 2; mi++) {
        const int lr0 = wm * 32 + mi * 16 + g;
        float tot0 = s_rs[lr0] + s_rs[MROWS + lr0] + s_rs[2 * MROWS + lr0] + s_rs[3 * MROWS + lr0];
        float tot1 = s_rs[lr0 + 8] + s_rs[MROWS + lr0 + 8] + s_rs[2 * MROWS + lr0 + 8] + s_rs[3 * MROWS + lr0 + 8];
        float red0 = (tot0 - 1.0f) * (1.0f / (float)PDIM);
        float red1 = (tot1 - 1.0f) * (1.0f / (float)PDIM);
        float* o0 = out + (size_t)(row0 + lr0) * PDIM;
        float* o1 = out + (size_t)(row0 + lr0 + 8) * PDIM;
#pragma unroll
        for (int ni = 0; ni < 8; ni++) {
            const int col = wn * 64 + ni * 8 + 2 * t;
            float2 v0, v1;
            v0.x = __logf(acc[mi][ni][0] - red0);
            v0.y = __logf(acc[mi][ni][1] - red0);
            v1.x = __logf(acc[mi][ni][2] - red1);
            v1.y = __logf(acc[mi][ni][3] - red1);
            *(float2*)(o0 + col) = v0;
            *(float2*)(o1 + col) = v1;
        }
    }
}

// ---------------- launch ----------------
extern "C" void kernel_launch(void* const* d_in, const int* in_sizes, int n_in,
                              void* d_out, int out_size) {
    const float* hs      = (const float*)d_in[0];
    const float* alloW   = (const float*)d_in[1];
    const int*   phone   = (const int*)d_in[2];
    const int*   phoneme = (const int*)d_in[3];
    float*       out     = (float*)d_out;
    (void)in_sizes; (void)n_in; (void)out_size;

    static bool attr_set = false;
    if (!attr_set) {
        cudaFuncSetAttribute(k_gemm, cudaFuncAttributeMaxDynamicSharedMemorySize, SMEM_GEMM);
        attr_set = true;
    }

    k_buildM<<<PDIM, 256>>>(alloW, phone, phoneme);
    k_gemm<<<NROWS / MROWS, 256, SMEM_GEMM>>>(hs, out);
}

// round 15
// speedup vs baseline: 1.6882x; 1.6882x over previous
#include <cuda_runtime.h>
#include <cuda_bf16.h>
#include <math.h>
#include <stdint.h>

// Problem constants (fixed shapes)
#define NROWS 16384     // B*T (GEMM M)
#define CDIM  512       // phones (GEMM K)
#define ADIM  4096      // arcs
#define PDIM  256       // phonemes (GEMM N)
#define NB    264       // padded N: col 256 = ones (row-sum column), 257-263 = zero

// ---------------- device scratch ----------------
__device__ __nv_bfloat16 g_M[NB * CDIM];   // dense matrix [n][c] (= B col-major), 264 KB

// ---------------- build dense M (264 blocks x 256 threads) ----------------
#define FXSCALE 16777216.0f
__global__ void __launch_bounds__(256) k_buildM(const float* __restrict__ alloW,
                                                const int* __restrict__ phone,
                                                const int* __restrict__ phoneme) {
    __shared__ int rowi[CDIM];
    const int p = blockIdx.x, t = threadIdx.x;

    if (p < PDIM) {
        rowi[t] = 0;
        rowi[t + 256] = 0;
        __syncthreads();
#pragma unroll 4
        for (int a = t; a < ADIM; a += 256) {
            if (phoneme[a] == p) {
                int fx = __float2int_rn(expf(alloW[a]) * FXSCALE);
                atomicAdd(&rowi[phone[a]], fx);
            }
        }
        __syncthreads();
    } else {
        const int v = (p == PDIM) ? (int)FXSCALE : 0;   // ones column / zero pad
        rowi[t] = v;
        rowi[t + 256] = v;
        __syncthreads();
    }

    g_M[(size_t)p * CDIM + t]       = __float2bfloat16_rn((float)rowi[t] * (1.0f / FXSCALE));
    g_M[(size_t)p * CDIM + t + 256] = __float2bfloat16_rn((float)rowi[t + 256] * (1.0f / FXSCALE));
}

// ---------------- fused exp + GEMM + epilogue (256 blocks x 256, occ 2) ----------------
// Tile 64x256(+sum col). sA holds UNNORMALIZED exp(h); row sums come out of the GEMM.
// smem: sA [64][520] bf16 = 66560 | sB 2 x [264][40] bf16 = 42240 -> 108800 B, 2 CTAs/SM.
#define MROWS 64
#define LDA2  520
#define LDB   40
#define KC    32
#define NKC   (CDIM / KC)      // 16
#define SA_BYTES (MROWS * LDA2 * 2)
#define SB_BYTES (NB * LDB * 2)
#define SMEM_GEMM (SA_BYTES + 2 * SB_BYTES)

__device__ __forceinline__ void mma16816(float* d, const uint32_t* a, const uint32_t* b) {
    asm volatile("mma.sync.aligned.m16n8k16.row.col.f32.bf16.bf16.f32 "
                 "{%0,%1,%2,%3}, {%4,%5,%6,%7}, {%8,%9}, {%0,%1,%2,%3};"
                 : "+f"(d[0]), "+f"(d[1]), "+f"(d[2]), "+f"(d[3])
                 : "r"(a[0]), "r"(a[1]), "r"(a[2]), "r"(a[3]), "r"(b[0]), "r"(b[1]));
}
__device__ __forceinline__ void ldsm_x4(uint32_t* r, uint32_t addr) {
    asm volatile("ldmatrix.sync.aligned.m8n8.x4.shared.b16 {%0,%1,%2,%3}, [%4];"
                 : "=r"(r[0]), "=r"(r[1]), "=r"(r[2]), "=r"(r[3]) : "r"(addr));
}
__device__ __forceinline__ void ldsm_x2(uint32_t* r, uint32_t addr) {
    asm volatile("ldmatrix.sync.aligned.m8n8.x2.shared.b16 {%0,%1}, [%2];"
                 : "=r"(r[0]), "=r"(r[1]) : "r"(addr));
}
__device__ __forceinline__ uint32_t smem_u32(const void* p) {
    uint32_t a;
    asm("{ .reg .u64 t; cvta.to.shared.u64 t, %1; cvt.u32.u64 %0, t; }" : "=r"(a) : "l"(p));
    return a;
}
__device__ __forceinline__ void cp16(uint32_t dst, const void* src) {
    asm volatile("cp.async.cg.shared.global [%0], [%1], 16;" :: "r"(dst), "l"(src));
}
#define CP_COMMIT() asm volatile("cp.async.commit_group;" ::: "memory")

__global__ void __launch_bounds__(256, 2) k_gemm(const float* __restrict__ hs,
                                                 float* __restrict__ out) {
    extern __shared__ char smem[];
    __nv_bfloat16* sA   = (__nv_bfloat16*)smem;                 // [64][LDA2]
    float*         s_rs = (float*)smem;                         // [512] reuse after mainloop

    const int tid  = threadIdx.x;
    const int warp = tid >> 5, lane = tid & 31;
    const int wm = warp >> 2, wn = warp & 3;   // 2 x 4 warp grid (32-row x 64-col warp tiles)
    const int g = lane >> 2, t = lane & 3;
    const int row0 = blockIdx.x * MROWS;
    const uint32_t sA_u32 = smem_u32(smem);
    const uint32_t sB_u32 = sA_u32 + SA_BYTES;

    // ldmatrix lane-address components
    const int a_row  = wm * 32 + (lane & 15);
    const int a_csel = (lane >> 4) << 3;
    const int b_row  = wn * 64 + (lane & 7);
    const int b_rowx = 256 + (lane & 7);       // ones/zero pad rows
    const int b_csel = (lane & 8);

    // ---- prefetch B chunk 0 (overlaps exp phase) ----
    for (int i = tid; i < NB * 4; i += 256) {
        int r = i >> 2, c = i & 3;
        cp16(sB_u32 + r * (LDB * 2) + c * 16, g_M + (size_t)r * CDIM + c * 8);
    }
    CP_COMMIT();

    // ---- exp phase: UNNORMALIZED exp(h) -> sA; no sums, no reductions ----
    for (int b = 0; b < 4; b++) {
        float4 v[2][4];
#pragma unroll
        for (int rr = 0; rr < 2; rr++) {
            const int row = warp * 8 + b * 2 + rr;
            const float4* hp = (const float4*)(hs + (size_t)(row0 + row) * CDIM);
#pragma unroll
            for (int s = 0; s < 4; s++) v[rr][s] = hp[s * 32 + lane];
        }
#pragma unroll
        for (int rr = 0; rr < 2; rr++) {
            const int row = warp * 8 + b * 2 + rr;
#pragma unroll
            for (int s = 0; s < 4; s++) {
                __nv_bfloat162 p0 = __floats2bfloat162_rn(__expf(v[rr][s].x), __expf(v[rr][s].y));
                __nv_bfloat162 p1 = __floats2bfloat162_rn(__expf(v[rr][s].z), __expf(v[rr][s].w));
                uint2 w;
                w.x = *(uint32_t*)&p0;
                w.y = *(uint32_t*)&p1;
                *(uint2*)(sA + row * LDA2 + s * 128 + lane * 4) = w;
            }
        }
    }
    __syncthreads();  // sA fully built

    // ---- mainloop: 16 K-chunks, depth-1 prefetch, one barrier per chunk ----
    float acc[2][8][4];
#pragma unroll
    for (int mi = 0; mi < 2; mi++)
#pragma unroll
        for (int ni = 0; ni < 8; ni++)
#pragma unroll
            for (int f = 0; f < 4; f++) acc[mi][ni][f] = 0.0f;
    float accS[2][4];   // ones-column partials (row sums)
#pragma unroll
    for (int mi = 0; mi < 2; mi++)
#pragma unroll
        for (int f = 0; f < 4; f++) accS[mi][f] = 0.0f;

#pragma unroll 1
    for (int kc = 0; kc < NKC; kc++) {
        asm volatile("cp.async.wait_group 0;" ::: "memory");
        __syncthreads();

        if (kc + 1 < NKC) {
            for (int i = tid; i < NB * 4; i += 256) {
                int r = i >> 2, c = i & 3;
                cp16(sB_u32 + ((kc + 1) & 1) * SB_BYTES + r * (LDB * 2) + c * 16,
                     g_M + (size_t)r * CDIM + (kc + 1) * KC + c * 8);
            }
            CP_COMMIT();
        }

        const uint32_t sBbuf = sB_u32 + (kc & 1) * SB_BYTES;
#pragma unroll
        for (int kt = 0; kt < KC / 16; kt++) {
            const int ktg  = kc * 2 + kt;
            const int kcol = ktg * 16;
            uint32_t afr[2][4], bfr[8][2];
#pragma unroll
            for (int mi = 0; mi < 2; mi++)
                ldsm_x4(afr[mi], sA_u32 + ((a_row + mi * 16) * LDA2 + kcol + a_csel) * 2);
#pragma unroll
            for (int ni = 0; ni < 8; ni++)
                ldsm_x2(bfr[ni], sBbuf + ((b_row + ni * 8) * LDB + kt * 16 + b_csel) * 2);

            const bool extra = (wn == (ktg & 3));   // rotate sum-column duty
            uint32_t bfrX[2];
            if (extra)
                ldsm_x2(bfrX, sBbuf + (b_rowx * LDB + kt * 16 + b_csel) * 2);

#pragma unroll
            for (int mi = 0; mi < 2; mi++)
#pragma unroll
                for (int ni = 0; ni < 8; ni++)
                    mma16816(acc[mi][ni], afr[mi], bfr[ni]);
            if (extra) {
                mma16816(accS[0], afr[0], bfrX);
                mma16816(accS[1], afr[1], bfrX);
            }
        }
    }
    __syncthreads();  // mainloop done; sA reusable as s_rs

    // ---- epilogue: tot partials (over N) + inv partials (ones column) ----
    float psum[2][2];
#pragma unroll
    for (int mi = 0; mi < 2; mi++) {
        float s0 = 0.0f, s1 = 0.0f;
#pragma unroll
        for (int ni = 0; ni < 8; ni++) {
            s0 += acc[mi][ni][0] + acc[mi][ni][1];
            s1 += acc[mi][ni][2] + acc[mi][ni][3];
        }
        s0 += __shfl_xor_sync(0xffffffffu, s0, 1);
        s0 += __shfl_xor_sync(0xffffffffu, s0, 2);
        s1 += __shfl_xor_sync(0xffffffffu, s1, 1);
        s1 += __shfl_xor_sync(0xffffffffu, s1, 2);
        psum[mi][0] = s0;
        psum[mi][1] = s1;
    }
    if (t == 0) {
#pragma unroll
        for (int mi = 0; mi < 2; mi++) {
            const int lr = wm * 32 + mi * 16 + g;
            s_rs[wn * MROWS + lr]           = psum[mi][0];
            s_rs[wn * MROWS + lr + 8]       = psum[mi][1];
            s_rs[256 + wn * MROWS + lr]     = accS[mi][0];   // col 256 partial (row lr)
            s_rs[256 + wn * MROWS + lr + 8] = accS[mi][2];   // col 256 partial (row lr+8)
        }
    }
    __syncthreads();

#pragma unroll
    for (int mi = 0; mi < 2; mi++) {
        const int lr0 = wm * 32 + mi * 16 + g;
        float tot0 = s_rs[lr0] + s_rs[MROWS + lr0] + s_rs[2 * MROWS + lr0] + s_rs[3 * MROWS + lr0];
        float tot1 = s_rs[lr0 + 8] + s_rs[MROWS + lr0 + 8] + s_rs[2 * MROWS + lr0 + 8] + s_rs[3 * MROWS + lr0 + 8];
        float rs0 = s_rs[256 + lr0] + s_rs[256 + MROWS + lr0] + s_rs[256 + 2 * MROWS + lr0] + s_rs[256 + 3 * MROWS + lr0];
        float rs1 = s_rs[256 + lr0 + 8] + s_rs[256 + MROWS + lr0 + 8] + s_rs[256 + 2 * MROWS + lr0 + 8] + s_rs[256 + 3 * MROWS + lr0 + 8];
        const float inv0 = 1.0f / rs0, inv1 = 1.0f / rs1;
        float red0 = (tot0 * inv0 - 1.0f) * (1.0f / (float)PDIM);
        float red1 = (tot1 * inv1 - 1.0f) * (1.0f / (float)PDIM);
        float* o0 = out + (size_t)(row0 + lr0) * PDIM;
        float* o1 = out + (size_t)(row0 + lr0 + 8) * PDIM;
#pragma unroll
        for (int ni = 0; ni < 8; ni++) {
            const int col = wn * 64 + ni * 8 + 2 * t;
            float2 v0, v1;
            v0.x = __logf(acc[mi][ni][0] * inv0 - red0);
            v0.y = __logf(acc[mi][ni][1] * inv0 - red0);
            v1.x = __logf(acc[mi][ni][2] * inv1 - red1);
            v1.y = __logf(acc[mi][ni][3] * inv1 - red1);
            *(float2*)(o0 + col) = v0;
            *(float2*)(o1 + col) = v1;
        }
    }
}

// ---------------- launch ----------------
extern "C" void kernel_launch(void* const* d_in, const int* in_sizes, int n_in,
                              void* d_out, int out_size) {
    const float* hs      = (const float*)d_in[0];
    const float* alloW   = (const float*)d_in[1];
    const int*   phone   = (const int*)d_in[2];
    const int*   phoneme = (const int*)d_in[3];
    float*       out     = (float*)d_out;
    (void)in_sizes; (void)n_in; (void)out_size;

    static bool attr_set = false;
    if (!attr_set) {
        cudaFuncSetAttribute(k_gemm, cudaFuncAttributeMaxDynamicSharedMemorySize, SMEM_GEMM);
        attr_set = true;
    }

    k_buildM<<<NB, 256>>>(alloW, phone, phoneme);
    k_gemm<<<NROWS / MROWS, 256, SMEM_GEMM>>>(hs, out);
}